// round 9
// baseline (speedup 1.0000x reference)
#include <cuda_runtime.h>
#include <cstdint>
#include <cstddef>

#define NROWS 8192
#define ROW_F4 2048              // NROWS/4
#define ROW_SHIFT 11
#define NN_F4 (NROWS * (size_t)NROWS / 4)
#define IDX_CAP 256              // max collected same-class columns per row (mean 64, 8-sigma safe)

__device__ unsigned char g_cls[NROWS];
__device__ float4        g_params[NROWS];  // {pg, ng, rv, pad}

// ---- fused prep: dtype probe + class pack + per-row counts ----
// 256 blocks x 256 threads; each block owns 32 rows (4 per warp).
__global__ __launch_bounds__(256) void k_prep(const int* __restrict__ w,
                                              const float* __restrict__ sim) {
    __shared__ unsigned int   sh_cls[ROW_F4];           // 8 KB packed class bytes
    __shared__ unsigned short sh_idx[8][IDX_CAP];       // matched columns per warp
    __shared__ int            sh_cnt[8];
    __shared__ int            sh32;
    int t = threadIdx.x;

    // dtype probe (in-bounds for both dtypes: words < NROWS):
    // int64 values in [0,128) => odd 32-bit words all zero; int32 => nonzero whp.
    if (t == 0) sh32 = 0;
    __syncthreads();
    if (t < 128 && w[2 * t + 1] != 0) sh32 = 1;
    __syncthreads();
    int is32 = sh32;

    // pack class bytes into smem words via int4 loads
    const int4* w4 = reinterpret_cast<const int4*>(w);
#pragma unroll
    for (int j = t; j < ROW_F4; j += 256) {
        int b0, b1, b2, b3;
        if (is32) {
            int4 v = w4[j];
            b0 = v.x; b1 = v.y; b2 = v.z; b3 = v.w;
        } else {
            int4 u = w4[2 * j];
            int4 v = w4[2 * j + 1];
            b0 = u.x; b1 = u.z; b2 = v.x; b3 = v.z;
        }
        sh_cls[j] = (unsigned int)(b0 & 255) | ((unsigned int)(b1 & 255) << 8) |
                    ((unsigned int)(b2 & 255) << 16) | ((unsigned int)(b3 & 255) << 24);
    }
    __syncthreads();

    int wid = t >> 5, lane = t & 31;

    for (int r = 0; r < 4; ++r) {
        int row = blockIdx.x * 32 + wid * 4 + r;
        unsigned int ci  = (sh_cls[row >> 2] >> ((row & 3) * 8)) & 255u;
        unsigned int ci4 = ci * 0x01010101u;

        if (lane == 0) sh_cnt[wid] = 0;
        __syncwarp();

        // phase 1: collect matched column indices (smem-only scan)
        for (int j = lane; j < ROW_F4; j += 32) {
            unsigned int m = __vcmpeq4(sh_cls[j], ci4);
            if (m) {
                int n = __popc(m) >> 3;
                int p = atomicAdd(&sh_cnt[wid], n);
                int c = 4 * j;
                if (m & 0x000000ffu) { if (p < IDX_CAP) sh_idx[wid][p] = (unsigned short)(c);     ++p; }
                if (m & 0x0000ff00u) { if (p < IDX_CAP) sh_idx[wid][p] = (unsigned short)(c + 1); ++p; }
                if (m & 0x00ff0000u) { if (p < IDX_CAP) sh_idx[wid][p] = (unsigned short)(c + 2); ++p; }
                if (m & 0xff000000u) { if (p < IDX_CAP) sh_idx[wid][p] = (unsigned short)(c + 3); ++p; }
            }
        }
        __syncwarp();
        int same_cnt = sh_cnt[wid];
        int lim = (same_cnt < IDX_CAP) ? same_cnt : IDX_CAP;

        // phase 2: dense gather -> high MLP
        const float* rowp = sim + (size_t)row * NROWS;
        int pc = 0;
        for (int l = lane; l < lim; l += 32)
            pc += (rowp[sh_idx[wid][l]] < 1.0f) ? 1 : 0;
        pc = __reduce_add_sync(0xffffffffu, pc);

        if (lane == 0) {
            int negraw = NROWS - same_cnt;
            float rv = (negraw > 0) ? 1.0f : 0.0f;
            float pg = -2.0f * rv / (float)((pc     > 1) ? pc     : 1);
            float ng = 40.0f * rv / (float)((negraw > 1) ? negraw : 1);
            g_params[row] = make_float4(pg, ng, rv, 0.0f);
            g_cls[row] = (unsigned char)ci;
        }
        __syncwarp();
    }
}

// ---- per-element math ----
__device__ __forceinline__ void elem(float simv, bool same,
                                     float pg, float ng, float rv,
                                     float& L, float& G) {
    float s = simv - 0.5f;
    float z = same ? (-2.0f * s) : (40.0f * s);
    bool active = (!same) || (simv < 1.0f);
    float t   = __expf(-fabsf(z));
    float op  = 1.0f + t;
    float inv = __fdividef(1.0f, op);
    float sp  = fmaxf(z, 0.0f) + __logf(op);          // stable softplus(z)
    float sg  = ((z >= 0.0f) ? 1.0f : t) * inv;       // stable sigmoid(z)
    float cf  = same ? pg : ng;
    L = active ? sp * rv : 0.0f;
    G = active ? cf * sg : 0.0f;
}

// ---- main streaming kernel: EXACT R3/R8 structure (117us, 80% DRAM) ----
__global__ __launch_bounds__(256) void k_main(const float* __restrict__ sim,
                                              float* __restrict__ out) {
    int idx  = blockIdx.x * blockDim.x + threadIdx.x;   // float4 index
    int row  = idx >> ROW_SHIFT;
    int col4 = idx & (ROW_F4 - 1);

    float4 sv = __ldcs(reinterpret_cast<const float4*>(sim) + idx);
    uchar4 cj = reinterpret_cast<const uchar4*>(g_cls)[col4];
    int    ci = g_cls[row];
    float4 p  = g_params[row];

    float4 Lo, Gr;
    elem(sv.x, cj.x == ci, p.x, p.y, p.z, Lo.x, Gr.x);
    elem(sv.y, cj.y == ci, p.x, p.y, p.z, Lo.y, Gr.y);
    elem(sv.z, cj.z == ci, p.x, p.y, p.z, Lo.z, Gr.z);
    elem(sv.w, cj.w == ci, p.x, p.y, p.z, Lo.w, Gr.w);

    float4* lossb = reinterpret_cast<float4*>(out);
    float4* gradb = lossb + NN_F4;
    __stcs(lossb + idx, Lo);
    __stcs(gradb + idx, Gr);
}

extern "C" void kernel_launch(void* const* d_in, const int* in_sizes, int n_in,
                              void* d_out, int out_size) {
    const float* sim = (const float*)d_in[0];
    const int*   tgw = (const int*)d_in[1];     // int32 view of targets
    float*       out = (float*)d_out;

    k_prep<<<256, 256>>>(tgw, sim);
    k_main<<<(int)(NN_F4 / 256), 256>>>(sim, out);
}

// round 10
// speedup vs baseline: 1.1253x; 1.1253x over previous
#include <cuda_runtime.h>
#include <cstdint>
#include <cstddef>

#define NROWS 8192
#define ROW_F4 2048              // NROWS/4
#define ROW_SHIFT 11
#define NN_F4 (NROWS * (size_t)NROWS / 4)
#define IDX_CAP 256              // max same-class columns per row (mean 64, ~24-sigma safe)

__device__ unsigned char g_cls[NROWS];     // class byte per row/col (also packed words)
__device__ float4        g_params[NROWS];  // {pg, ng, rv, pad}

// ---- class extraction with in-bounds dtype probe (measured ~4.8us) ----
// View targets as int32 words. Probe ONLY words < NROWS (in-bounds for both
// dtypes): int64 values in [0,128) => odd words all zero; int32 targets =>
// P(128 consecutive odd words zero) = 128^-128 ~ 0.
__global__ __launch_bounds__(256) void k_cls(const int* __restrict__ w) {
    __shared__ int sh32;
    int t    = threadIdx.x;
    int base = blockIdx.x * 256;
    if (t == 0) sh32 = 0;
    __syncthreads();
    if (t < 128 && w[2 * t + 1] != 0) sh32 = 1;
    __syncthreads();
    int i = base + t;
    int c = sh32 ? w[i] : w[2 * i];
    g_cls[i] = (unsigned char)c;
}

// ---- prep: per-row {pos_cnt, same_cnt} -> params ----
// 1024 blocks x 8 warps, ONE row per warp (high SM-wide parallelism).
// Class words come from g_cls re-read as int4 (8 KB, L2-hot): 2 loads/thread.
__global__ __launch_bounds__(256) void k_prep(const float* __restrict__ sim) {
    __shared__ unsigned int   sh_cls[ROW_F4];      // 8 KB packed class bytes
    __shared__ unsigned short sh_idx[8][IDX_CAP];  // matched columns per warp
    __shared__ int            sh_cnt[8];
    int t = threadIdx.x;

    // load packed class words: 512 int4 / 256 threads = 2 per thread
    const int4* cw4 = reinterpret_cast<const int4*>(g_cls);
    int4* sh4 = reinterpret_cast<int4*>(sh_cls);
    sh4[t]       = cw4[t];
    sh4[t + 256] = cw4[t + 256];
    __syncthreads();

    int wid = t >> 5, lane = t & 31;
    int row = blockIdx.x * 8 + wid;
    unsigned int ci  = (sh_cls[row >> 2] >> ((row & 3) * 8)) & 255u;
    unsigned int ci4 = ci * 0x01010101u;

    if (lane == 0) sh_cnt[wid] = 0;
    __syncwarp();

    // phase 1: collect matched column indices (smem-only scan, 64 iters/lane)
    for (int j = lane; j < ROW_F4; j += 32) {
        unsigned int m = __vcmpeq4(sh_cls[j], ci4);
        if (m) {
            int n = __popc(m) >> 3;
            int p = atomicAdd(&sh_cnt[wid], n);
            int c = 4 * j;
            if (m & 0x000000ffu) { if (p < IDX_CAP) sh_idx[wid][p] = (unsigned short)(c);     ++p; }
            if (m & 0x0000ff00u) { if (p < IDX_CAP) sh_idx[wid][p] = (unsigned short)(c + 1); ++p; }
            if (m & 0x00ff0000u) { if (p < IDX_CAP) sh_idx[wid][p] = (unsigned short)(c + 2); ++p; }
            if (m & 0xff000000u) { if (p < IDX_CAP) sh_idx[wid][p] = (unsigned short)(c + 3); ++p; }
        }
    }
    __syncwarp();
    int same_cnt = sh_cnt[wid];
    int lim = (same_cnt < IDX_CAP) ? same_cnt : IDX_CAP;

    // phase 2: dense gather -> all scattered loads in flight together
    const float* rowp = sim + (size_t)row * NROWS;
    int pc = 0;
    for (int l = lane; l < lim; l += 32)
        pc += (rowp[sh_idx[wid][l]] < 1.0f) ? 1 : 0;
    pc = __reduce_add_sync(0xffffffffu, pc);

    if (lane == 0) {
        int negraw = NROWS - same_cnt;
        float rv = (negraw > 0) ? 1.0f : 0.0f;
        float pg = -2.0f * rv / (float)((pc     > 1) ? pc     : 1);
        float ng = 40.0f * rv / (float)((negraw > 1) ? negraw : 1);
        g_params[row] = make_float4(pg, ng, rv, 0.0f);
    }
}

// ---- per-element math ----
__device__ __forceinline__ void elem(float simv, bool same,
                                     float pg, float ng, float rv,
                                     float& L, float& G) {
    float s = simv - 0.5f;
    float z = same ? (-2.0f * s) : (40.0f * s);
    bool active = (!same) || (simv < 1.0f);
    float t   = __expf(-fabsf(z));
    float op  = 1.0f + t;
    float inv = __fdividef(1.0f, op);
    float sp  = fmaxf(z, 0.0f) + __logf(op);          // stable softplus(z)
    float sg  = ((z >= 0.0f) ? 1.0f : t) * inv;       // stable sigmoid(z)
    float cf  = same ? pg : ng;
    L = active ? sp * rv : 0.0f;
    G = active ? cf * sg : 0.0f;
}

// ---- main streaming kernel: EXACT R3/R8/R9 structure (115-117us, 81% DRAM) ----
__global__ __launch_bounds__(256) void k_main(const float* __restrict__ sim,
                                              float* __restrict__ out) {
    int idx  = blockIdx.x * blockDim.x + threadIdx.x;   // float4 index
    int row  = idx >> ROW_SHIFT;
    int col4 = idx & (ROW_F4 - 1);

    float4 sv = __ldcs(reinterpret_cast<const float4*>(sim) + idx);
    uchar4 cj = reinterpret_cast<const uchar4*>(g_cls)[col4];
    int    ci = g_cls[row];
    float4 p  = g_params[row];

    float4 Lo, Gr;
    elem(sv.x, cj.x == ci, p.x, p.y, p.z, Lo.x, Gr.x);
    elem(sv.y, cj.y == ci, p.x, p.y, p.z, Lo.y, Gr.y);
    elem(sv.z, cj.z == ci, p.x, p.y, p.z, Lo.z, Gr.z);
    elem(sv.w, cj.w == ci, p.x, p.y, p.z, Lo.w, Gr.w);

    float4* lossb = reinterpret_cast<float4*>(out);
    float4* gradb = lossb + NN_F4;
    __stcs(lossb + idx, Lo);
    __stcs(gradb + idx, Gr);
}

extern "C" void kernel_launch(void* const* d_in, const int* in_sizes, int n_in,
                              void* d_out, int out_size) {
    const float* sim = (const float*)d_in[0];
    const int*   tgw = (const int*)d_in[1];     // int32 view of targets
    float*       out = (float*)d_out;

    k_cls<<<NROWS / 256, 256>>>(tgw);
    k_prep<<<NROWS / 8, 256>>>(sim);
    k_main<<<(int)(NN_F4 / 256), 256>>>(sim, out);
}